// round 15
// baseline (speedup 1.0000x reference)
#include <cuda_runtime.h>
#include <cstdint>

#define BB 64
#define SS 20
#define WW 1024
#define NC 80
#define DL 300
#define DE 128
#define NBLK 512               // split-K blocks for the big GEMM
#define KTOT (WW*DE)           // 131072
#define KC (KTOT/NBLK)         // 256 K per block

// ---- output layout (flattened tuple, in reference return order) ----
#define OFF_OUT   0
#define OFF_FEAT  (BB*NC)                       // 5120
#define OFF_WP    (OFF_FEAT + BB*DE)            // 13312
#define OFF_ADJ   (OFF_WP + BB*WW)              // 78848
#define OFF_WPROB (OFF_ADJ + BB*WW*WW)          // 67187712

// ---- device scratch (no allocations allowed) ----
__device__ int   d_mh[BB*WW];
__device__ float d_wc[BB*NC];
__device__ float d_wp[BB*WW];
__device__ float d_u [BB*WW];
__device__ float d_v [BB*WW];
__device__ float d_s0[DE];
__device__ float d_s1[DE];
__device__ float d_scratch[NBLK*BB*DE];   // 16 MB split-K partials
__device__ float d_feat[BB*DE];

__device__ __forceinline__ float lrelu(float x) { return x > 0.f ? x : 0.01f * x; }

// ---------------------------------------------------------------
// 0. zero multi-hot
__global__ void k_zero() {
    int i = blockIdx.x * 256 + threadIdx.x;
    if (i < BB*WW) d_mh[i] = 0;
}

// 1. argmax over W per (b,s<k), set multi-hot. One warp per (b,s).
__global__ void k_argmax(const float* __restrict__ wr, const int* __restrict__ kptr) {
    int gw   = blockIdx.x * 8 + (threadIdx.x >> 5);
    int lane = threadIdx.x & 31;
    if (gw >= BB*SS) return;
    int b = gw / SS, s = gw % SS;
    int kk = kptr ? min(*kptr, SS) : SS;
    if (s >= kk) return;
    const float* row = wr + (size_t)(b*SS + s) * WW;
    float best = row[lane]; int bi = lane;
    for (int w = lane + 32; w < WW; w += 32) {
        float x = row[w];
        if (x > best) { best = x; bi = w; }   // strict > keeps first index (jnp.argmax)
    }
    #pragma unroll
    for (int off = 16; off; off >>= 1) {
        float ov = __shfl_down_sync(0xffffffffu, best, off);
        int   oi = __shfl_down_sync(0xffffffffu, bi,   off);
        if (ov > best || (ov == best && oi < bi)) { best = ov; bi = oi; }
    }
    if (lane == 0) d_mh[b*WW + bi] = 1;
}

// 2. weight_cls = softmax(mh @ w_sl^T + b_sl). Block per b, 128 threads.
__global__ void k_softmax(const float* __restrict__ w_sl, const float* __restrict__ b_sl) {
    int b = blockIdx.x, tid = threadIdx.x;
    __shared__ int   sel[32];
    __shared__ int   cnt;
    __shared__ float red[128];
    if (tid == 0) cnt = 0;
    __syncthreads();
    for (int w = tid; w < WW; w += 128)
        if (d_mh[b*WW + w]) { int p = atomicAdd(&cnt, 1); sel[p] = w; }
    __syncthreads();
    int n = cnt;
    float logit = -1e30f;
    if (tid < NC) {
        logit = b_sl[tid];
        for (int j = 0; j < n; j++) logit += w_sl[tid*WW + sel[j]];
    }
    red[tid] = logit;  __syncthreads();
    for (int s = 64; s; s >>= 1) { if (tid < s) red[tid] = fmaxf(red[tid], red[tid+s]); __syncthreads(); }
    float mx = red[0]; __syncthreads();
    float e = (tid < NC) ? expf(logit - mx) : 0.f;
    red[tid] = e;      __syncthreads();
    for (int s = 64; s; s >>= 1) { if (tid < s) red[tid] += red[tid+s]; __syncthreads(); }
    float inv = 1.f / red[0];
    if (tid < NC) d_wc[b*NC + tid] = e * inv;
}

// 3. weight_pri + per-b reductions + (u,v) coefficients. Block per b, 256 threads.
__global__ void k_wpuv(const float* __restrict__ msl, const float* __restrict__ beta,
                       float* __restrict__ out) {
    int b = blockIdx.x, tid = threadIdx.x;
    __shared__ float wcs[NC];
    __shared__ float r0[256], r1[256], r2[256];
    if (tid < NC) wcs[tid] = d_wc[b*NC + tid];
    __syncthreads();
    float wpv[4]; int mhv[4];
    float lsum = 0.f, lsum1 = 0.f, lcnt = 0.f;
    #pragma unroll
    for (int r = 0; r < 4; r++) {
        int w = tid + r*256;
        float acc = 0.f;
        #pragma unroll 8
        for (int c = 0; c < NC; c++) acc = fmaf(wcs[c], msl[c*WW + w], acc);
        wpv[r] = acc;
        int m = d_mh[b*WW + w]; mhv[r] = m;
        d_wp[b*WW + w] = acc;
        out[OFF_WP + b*WW + w] = acc;           // weight_pri output
        lsum += acc;
        if (m) { lsum1 += acc; lcnt += 1.f; }
    }
    r0[tid] = lsum; r1[tid] = lsum1; r2[tid] = lcnt;
    __syncthreads();
    for (int s = 128; s; s >>= 1) {
        if (tid < s) { r0[tid] += r0[tid+s]; r1[tid] += r1[tid+s]; r2[tid] += r2[tid+s]; }
        __syncthreads();
    }
    float sumwp = r0[0], A1 = r1[0], nsel = r2[0];
    float A0 = sumwp - A1;
    float bp = *beta;
    #pragma unroll
    for (int r = 0; r < 4; r++) {
        int w = tid + r*256;
        float wp = wpv[r];
        float u, v;
        if (mhv[r]) { u = (1.f-bp)*nsel + bp*wp*A1; v = bp*wp*A0; }
        else        { u = bp*wp*A1;                 v = (1.f-bp) + bp*wp*A0; }
        d_u[b*WW + w] = u;
        d_v[b*WW + w] = v;
    }
}

// 4. s0/s1 = emb_table[{0,1}] @ w_lw^T + b_lw. One block, 256 threads.
__global__ void k_s01(const float* __restrict__ emb, const float* __restrict__ w_lw,
                      const float* __restrict__ b_lw) {
    int tid = threadIdx.x;
    int m = tid >> 7, d = tid & 127;
    const float* er = emb + m*DL;
    const float* wr = w_lw + d*DL;
    float acc = b_lw[d];
    for (int l = 0; l < DL; l++) acc = fmaf(er[l], wr[l], acc);
    if (m == 0) d_s0[d] = acc; else d_s1[d] = acc;
}

// 5. adj_pri = wp ⊗ wp, 256 MB of float4 stores. Block = (b, 16-row chunk).
__global__ void k_adj(float* __restrict__ out) {
    int b = blockIdx.x >> 6, ic = blockIdx.x & 63, tid = threadIdx.x; // 256 thr
    __shared__ float swp[WW];
    #pragma unroll
    for (int r = 0; r < 4; r++) swp[tid + r*256] = d_wp[b*WW + tid + r*256];
    __syncthreads();
    float4 wj = *(const float4*)&swp[tid*4];
    float4* op = (float4*)(out + OFF_ADJ + (size_t)b*WW*WW);
    #pragma unroll
    for (int r = 0; r < 16; r++) {
        int i = ic*16 + r;
        float wi = swp[i];
        float4 v = make_float4(wi*wj.x, wi*wj.y, wi*wj.z, wi*wj.w);
        op[(size_t)i*(WW/4) + tid] = v;
    }
}

// 6. word_prob gather
__global__ void k_wprob(const float* __restrict__ cwp, const int* __restrict__ label,
                        float* __restrict__ out) {
    int b = blockIdx.x, tid = threadIdx.x; // 256
    int lab = label[b];
    #pragma unroll
    for (int r = 0; r < 4; r++) {
        int w = tid + r*256;
        out[OFF_WPROB + b*WW + w] = cwp[(size_t)lab*WW + w];
    }
}

// 7. Big GEMM: feat_pre[b,e] = sum_k lrelu(u*s1+v*s0) * w_gcn[e,k].
//    Split-K over NBLK blocks; A generated on the fly into SMEM; f32x2 packed FMA.
__global__ void __launch_bounds__(128) k_gemm(const float* __restrict__ wgcn) {
    __shared__ float As[32][64];      // [k][b]
    __shared__ float Gs[32][128];     // [k][e]
    __shared__ float s0s[DE], s1s[DE];
    __shared__ float us2[128], vs2[128];
    const int tid = threadIdx.x;
    const int kb  = blockIdx.x;

    s0s[tid] = d_s0[tid & 127];
    s1s[tid] = d_s1[tid & 127];
    {
        int b = tid & 63, ii = tid >> 6;
        us2[tid] = d_u[b*WW + kb*2 + ii];
        vs2[tid] = d_v[b*WW + kb*2 + ii];
    }

    unsigned long long acc[8][4];     // 8 b-rows x 4 f32x2 (8 e-cols)
    #pragma unroll
    for (int i = 0; i < 8; i++)
        #pragma unroll
        for (int j = 0; j < 4; j++) acc[i][j] = 0ULL;

    const int bg  = tid & 7;          // b-group: rows bg*8..bg*8+7
    const int eg  = tid >> 3;         // e-group: cols eg*8..eg*8+7
    const int ab  = tid & 63;         // A-fill column (b)
    const int ak0 = tid >> 6;         // A-fill row parity

    #pragma unroll 1
    for (int p = 0; p < KC/32; p++) {
        const int kg0 = kb*KC + p*32;
        const int i   = kg0 >> 7;     // word index (constant within phase)
        const int d0  = kg0 & 127;    // embed-dim offset
        const int ii  = i - kb*2;
        __syncthreads();
        // G tile: thread t owns row e=t; 8 float4 from one contiguous 128B span
        {
            const float4* gp = (const float4*)(wgcn + (size_t)tid*KTOT + kg0);
            #pragma unroll
            for (int q = 0; q < 8; q++) {
                float4 g = gp[q];
                Gs[q*4+0][tid] = g.x;
                Gs[q*4+1][tid] = g.y;
                Gs[q*4+2][tid] = g.z;
                Gs[q*4+3][tid] = g.w;
            }
        }
        // A tile: lrelu(u*s1[d] + v*s0[d])
        {
            float uu = us2[ii*64 + ab];
            float vv = vs2[ii*64 + ab];
            #pragma unroll
            for (int j = 0; j < 16; j++) {
                int kk = ak0 + j*2;
                float x = fmaf(uu, s1s[d0+kk], vv * s0s[d0+kk]);
                As[kk][ab] = lrelu(x);
            }
        }
        __syncthreads();
        #pragma unroll 4
        for (int kk = 0; kk < 32; kk++) {
            float4 a0 = *(const float4*)&As[kk][bg*8];
            float4 a1 = *(const float4*)&As[kk][bg*8 + 4];
            ulonglong2 g01 = *(const ulonglong2*)&Gs[kk][eg*8];
            ulonglong2 g23 = *(const ulonglong2*)&Gs[kk][eg*8 + 4];
            float av[8] = {a0.x, a0.y, a0.z, a0.w, a1.x, a1.y, a1.z, a1.w};
            #pragma unroll
            for (int bb = 0; bb < 8; bb++) {
                unsigned long long a2;
                asm("mov.b64 %0, {%1, %1};" : "=l"(a2) : "r"(__float_as_uint(av[bb])));
                asm("fma.rn.f32x2 %0, %1, %2, %0;" : "+l"(acc[bb][0]) : "l"(a2), "l"(g01.x));
                asm("fma.rn.f32x2 %0, %1, %2, %0;" : "+l"(acc[bb][1]) : "l"(a2), "l"(g01.y));
                asm("fma.rn.f32x2 %0, %1, %2, %0;" : "+l"(acc[bb][2]) : "l"(a2), "l"(g23.x));
                asm("fma.rn.f32x2 %0, %1, %2, %0;" : "+l"(acc[bb][3]) : "l"(a2), "l"(g23.y));
            }
        }
    }
    // write split-K partials (deterministic; no atomics)
    float* sp = d_scratch + (size_t)kb * (BB*DE);
    #pragma unroll
    for (int bb = 0; bb < 8; bb++) {
        int b = bg*8 + bb;
        #pragma unroll
        for (int j = 0; j < 4; j++) {
            unsigned int lo, hi;
            asm("mov.b64 {%0, %1}, %2;" : "=r"(lo), "=r"(hi) : "l"(acc[bb][j]));
            int e = eg*8 + j*2;
            sp[b*DE + e]     = __uint_as_float(lo);
            sp[b*DE + e + 1] = __uint_as_float(hi);
        }
    }
}

// 8. reduce split-K, bias, leaky-relu -> feat
__global__ void k_red(const float* __restrict__ b_gcn, float* __restrict__ out) {
    int idx = blockIdx.x * 256 + threadIdx.x; // 8192 = B*DE
    float s = 0.f;
    const float* p = d_scratch + idx;
    #pragma unroll 8
    for (int j = 0; j < NBLK; j++) s += p[(size_t)j * (BB*DE)];
    float f = lrelu(s + b_gcn[idx & (DE-1)]);
    d_feat[idx] = f;
    out[OFF_FEAT + idx] = f;
}

// 9. output = feat @ w_cls^T + b_cls
__global__ void k_out(const float* __restrict__ w_cls, const float* __restrict__ b_cls,
                      float* __restrict__ out) {
    int b = blockIdx.x, tid = threadIdx.x; // 128
    __shared__ float f[DE];
    f[tid] = d_feat[b*DE + tid];
    __syncthreads();
    if (tid < NC) {
        float acc = b_cls[tid];
        #pragma unroll 8
        for (int e = 0; e < DE; e++) acc = fmaf(f[e], w_cls[tid*DE + e], acc);
        out[b*NC + tid] = acc;
    }
}

extern "C" void kernel_launch(void* const* d_in, const int* in_sizes, int n_in,
                              void* d_out, int out_size) {
    const float* word_recon = (const float*)d_in[0];
    const float* beta       = (const float*)d_in[1];
    const float* msl        = (const float*)d_in[2];
    const float* cwp        = (const float*)d_in[3];
    const float* emb        = (const float*)d_in[4];
    const float* w_sl       = (const float*)d_in[5];
    const float* b_sl       = (const float*)d_in[6];
    const float* w_lw       = (const float*)d_in[7];
    const float* b_lw       = (const float*)d_in[8];
    const float* wgcn       = (const float*)d_in[9];
    const float* b_gcn      = (const float*)d_in[10];
    const float* w_cls      = (const float*)d_in[11];
    const float* b_cls      = (const float*)d_in[12];
    const int*   label      = (const int*)d_in[13];
    const int*   kptr       = (n_in > 14) ? (const int*)d_in[14] : nullptr;
    float* out = (float*)d_out;

    k_zero   <<<(BB*WW + 255)/256, 256>>>();
    k_argmax <<<(BB*SS + 7)/8, 256>>>(word_recon, kptr);
    k_softmax<<<BB, 128>>>(w_sl, b_sl);
    k_wpuv   <<<BB, 256>>>(msl, beta, out);
    k_s01    <<<1, 256>>>(emb, w_lw, b_lw);
    k_adj    <<<BB*64, 256>>>(out);
    k_wprob  <<<BB, 256>>>(cwp, label, out);
    k_gemm   <<<NBLK, 128>>>(wgcn);
    k_red    <<<(BB*DE)/256, 256>>>(b_gcn, out);
    k_out    <<<BB, 128>>>(w_cls, b_cls, out);
}